// round 11
// baseline (speedup 1.0000x reference)
#include <cuda_runtime.h>
#include <cuda_fp16.h>
#include <cstdint>

// ============================================================================
// PhaseCoherenceComputer: C[bh,q,k] = mean_h cos(phq - phk)
//   = (cos_q @ cos_k^T + sin_q @ sin_k^T) / 64
// 16 GEMMs [2048,128]@[128,2048]^T in fp16 (validated rel_err ~5.6e-5).
// 1/64 folded into A scratch. Scratch row (K=128 fp16): cos[0:64] sin[64:128].
// R11: fat-warp variant. CTA tile 128x256 (2x4 warps of 64x64, 128 acc regs,
// 1 CTA/SM). LDSM.x4 per MMA drops 0.375 -> 0.25 (mainloop smem traffic -33%).
// K split into two cp.async groups (compute starts after first half lands).
// ============================================================================

#define NBH 16
#define SEQ 2048
#define NH  64
#define KS  128          // scratch K width (cos 64 | sin 64)
#define BM  128
#define BN  256

// ---------------- scratch (device globals; no allocation APIs) --------------
__device__ __align__(16) __half gA[NBH * SEQ * KS];   // 8 MB (pre-scaled 1/64)
__device__ __align__(16) __half gB[NBH * SEQ * KS];   // 8 MB

__device__ __forceinline__ uint32_t smem_u32(const void* p) {
    uint32_t a;
    asm("{ .reg .u64 t; cvta.to.shared.u64 t, %1; cvt.u32.u64 %0, t; }"
        : "=r"(a) : "l"(p));
    return a;
}

#define CP_ASYNC_16(smem, gptr)                                                \
    asm volatile("cp.async.cg.shared.global [%0], [%1], 16;"                   \
                 :: "r"(smem), "l"(gptr))
#define CP_COMMIT()  asm volatile("cp.async.commit_group;" ::: "memory")
#define CP_WAIT(N)   asm volatile("cp.async.wait_group %0;" :: "n"(N) : "memory")

#define LDSM_X4(r0, r1, r2, r3, addr)                                          \
    asm volatile("ldmatrix.sync.aligned.m8n8.x4.shared.b16 {%0,%1,%2,%3}, [%4];" \
                 : "=r"(r0), "=r"(r1), "=r"(r2), "=r"(r3) : "r"(addr))

#define MMA_F16(c0, c1, c2, c3, a0, a1, a2, a3, b0, b1)                        \
    asm volatile("mma.sync.aligned.m16n8k16.row.col.f32.f16.f16.f32 "          \
                 "{%0,%1,%2,%3}, {%4,%5,%6,%7}, {%8,%9}, {%0,%1,%2,%3};"       \
                 : "+f"(c0), "+f"(c1), "+f"(c2), "+f"(c3)                      \
                 : "r"(a0), "r"(a1), "r"(a2), "r"(a3), "r"(b0), "r"(b1))

#define STG_CS_V2(gptr, x, y)                                                  \
    asm volatile("st.global.cs.v2.f32 [%0], {%1,%2};"                          \
                 :: "l"(gptr), "f"(x), "f"(y) : "memory")

// ============================================================================
// Kernel 1: __sincosf -> fp16 scratch (A pre-scaled 1/NH). 4 harmonics/thread.
// ============================================================================
__global__ void phase_prep_kernel(const float* __restrict__ q,
                                  const float* __restrict__ k)
{
    const int NT = NBH * SEQ * (NH / 4);    // 524288 threads per tensor
    int idx = blockIdx.x * blockDim.x + threadIdx.x;
    if (idx >= 2 * NT) return;
    bool isQ = idx < NT;
    int li  = isQ ? idx : idx - NT;
    int row = li >> 4;
    int h4  = (li & 15) << 2;

    const float4 v = *(const float4*)((isQ ? q : k) + (size_t)row * NH + h4);
    const float sc = isQ ? (1.0f / (float)NH) : 1.0f;

    float s0, c0, s1, c1, s2, c2, s3, c3;
    __sincosf(v.x, &s0, &c0);
    __sincosf(v.y, &s1, &c1);
    __sincosf(v.z, &s2, &c2);
    __sincosf(v.w, &s3, &c3);

    __half2 ca = __floats2half2_rn(c0 * sc, c1 * sc);
    __half2 cb = __floats2half2_rn(c2 * sc, c3 * sc);
    __half2 sa = __floats2half2_rn(s0 * sc, s1 * sc);
    __half2 sb = __floats2half2_rn(s2 * sc, s3 * sc);

    __half* dst = (isQ ? gA : gB) + (size_t)row * KS;
    uint2 uc, us;
    uc.x = *reinterpret_cast<uint32_t*>(&ca);
    uc.y = *reinterpret_cast<uint32_t*>(&cb);
    us.x = *reinterpret_cast<uint32_t*>(&sa);
    us.y = *reinterpret_cast<uint32_t*>(&sb);
    *(uint2*)(dst + h4)      = uc;
    *(uint2*)(dst + 64 + h4) = us;
}

// ============================================================================
// Kernel 2: fp16 mma.sync GEMM, CTA tile 128x256, warp tile 64x64.
// grid = (8,16,16) = 2048 CTAs, 256 threads (2x4 warp grid).
// smem: A 128x256B (32KB) + B 256x256B (64KB) = 96KB, 1 CTA/SM.
// K loaded as two 64-wide cp.async groups; slices 0-3 run on group 0.
// ============================================================================
#define A_BYTES (BM * 256)                    // 32768
#define B_BYTES (BN * 256)                    // 65536
#define SMEM_TOTAL (A_BYTES + B_BYTES)        // 98304

__global__ void __launch_bounds__(256, 1)
phase_gemm_kernel(float* __restrict__ out)
{
    extern __shared__ char smem[];
    const uint32_t sb = smem_u32(smem);
    const int tid  = threadIdx.x;
    const int wid  = tid >> 5;
    const int lane = tid & 31;
    const int wm   = wid >> 2;          // 0-1
    const int wn   = wid & 3;           // 0-3

    const int nt = blockIdx.x;          // 256-wide N tile
    const int mt = blockIdx.y;
    const int bh = blockIdx.z;

    const __half* __restrict__ pA = gA + ((size_t)bh * SEQ + (size_t)mt * BM) * KS;
    const __half* __restrict__ pB = gB + ((size_t)bh * SEQ + (size_t)nt * BN) * KS;

    // gmem->smem: rows of 256B = 16 chunks; stage s covers chunks s*8..s*8+7.
    // thread -> (row = idx>>3, c = (idx&7)+s*8), idx = tid + t*256.
    const int lr = tid >> 3;             // base row (advance 32/t)
    const int lc = tid & 7;              // chunk within stage half

    // ---- stage 0 (k 0:64) for A and B, then stage 1 (k 64:128) ----
#pragma unroll
    for (int s = 0; s < 2; s++) {
        const int c = lc + s * 8;
        // A: 128 rows -> 4 iters; B: 256 rows -> 8 iters
#pragma unroll
        for (int t = 0; t < 4; t++) {
            int row = lr + t * 32;
            uint32_t sw = (uint32_t)((c & 8) | ((c & 7) ^ (row & 7)));
            CP_ASYNC_16(sb + row * 256 + (sw << 4), pA + (size_t)row * KS + c * 8);
        }
#pragma unroll
        for (int t = 0; t < 8; t++) {
            int row = lr + t * 32;
            uint32_t sw = (uint32_t)((c & 8) | ((c & 7) ^ (row & 7)));
            CP_ASYNC_16(sb + A_BYTES + row * 256 + (sw << 4),
                        pB + (size_t)row * KS + c * 8);
        }
        CP_COMMIT();
    }

    // ldmatrix base rows
    const int rl = lane & 15;
    const int hc = lane >> 4;
    uint32_t aRow[4], bRow[4];
#pragma unroll
    for (int mf = 0; mf < 4; mf++) aRow[mf] = (uint32_t)(wm * 64 + mf * 16 + rl);
#pragma unroll
    for (int p = 0; p < 4; p++)   bRow[p]  = (uint32_t)(wn * 64 + p * 16 + rl);

    float acc[4][8][4];
#pragma unroll
    for (int mf = 0; mf < 4; mf++)
#pragma unroll
        for (int nf = 0; nf < 8; nf++)
#pragma unroll
            for (int j = 0; j < 4; j++) acc[mf][nf][j] = 0.0f;

    // ---- mainloop: 8 k-slices; wait group0 before slice 0, all before 4 ----
#pragma unroll
    for (int kk = 0; kk < 8; kk++) {
        if (kk == 0) { CP_WAIT(1); __syncthreads(); }
        if (kk == 4) { CP_WAIT(0); __syncthreads(); }

        const uint32_t ch = (uint32_t)(kk * 2 + hc);   // 0-15
        uint32_t a[4][4];
#pragma unroll
        for (int mf = 0; mf < 4; mf++) {
            uint32_t r = aRow[mf];
            uint32_t sw = (ch & 8) | ((ch & 7) ^ (r & 7));
            LDSM_X4(a[mf][0], a[mf][1], a[mf][2], a[mf][3],
                    sb + r * 256 + (sw << 4));
        }
        uint32_t b[8][2];
#pragma unroll
        for (int p = 0; p < 4; p++) {
            uint32_t r = bRow[p];
            uint32_t sw = (ch & 8) | ((ch & 7) ^ (r & 7));
            uint32_t x0, x1, x2, x3;
            LDSM_X4(x0, x1, x2, x3, sb + A_BYTES + r * 256 + (sw << 4));
            b[p * 2][0]     = x0; b[p * 2][1]     = x2;
            b[p * 2 + 1][0] = x1; b[p * 2 + 1][1] = x3;
        }
#pragma unroll
        for (int mf = 0; mf < 4; mf++)
#pragma unroll
            for (int nf = 0; nf < 8; nf++)
                MMA_F16(acc[mf][nf][0], acc[mf][nf][1],
                        acc[mf][nf][2], acc[mf][nf][3],
                        a[mf][0], a[mf][1], a[mf][2], a[mf][3],
                        b[nf][0], b[nf][1]);
    }

    // ---- epilogue: direct .cs scatter (scale pre-folded into A) ----
    const int qg  = lane >> 2;
    const int cp2 = (lane & 3) * 2;
    float* obase = out + ((size_t)bh * SEQ + (size_t)mt * BM + wm * 64) * SEQ
                       + (size_t)nt * BN + wn * 64;
#pragma unroll
    for (int mf = 0; mf < 4; mf++) {
#pragma unroll
        for (int nf = 0; nf < 8; nf++) {
            float* p0 = obase + (size_t)(mf * 16 + qg) * SEQ + nf * 8 + cp2;
            STG_CS_V2(p0,           acc[mf][nf][0], acc[mf][nf][1]);
            STG_CS_V2(p0 + 8 * SEQ, acc[mf][nf][2], acc[mf][nf][3]);
        }
    }
}

// ============================================================================
// launch
// ============================================================================
extern "C" void kernel_launch(void* const* d_in, const int* in_sizes, int n_in,
                              void* d_out, int out_size)
{
    const float* q = (const float*)d_in[0];
    const float* k = (const float*)d_in[1];
    float* out = (float*)d_out;

    cudaFuncSetAttribute(phase_gemm_kernel,
                         cudaFuncAttributeMaxDynamicSharedMemorySize, SMEM_TOTAL);

    const int NT = NBH * SEQ * (NH / 4);
    int threads = 256;
    int blocks = (2 * NT + threads - 1) / threads;
    phase_prep_kernel<<<blocks, threads>>>(q, k);

    dim3 grid(SEQ / BN, SEQ / BM, NBH);   // (8,16,16)
    phase_gemm_kernel<<<grid, 256, SMEM_TOTAL>>>(out);
}

// round 12
// speedup vs baseline: 1.1642x; 1.1642x over previous
#include <cuda_runtime.h>
#include <cuda_fp16.h>
#include <cstdint>

// ============================================================================
// PhaseCoherenceComputer: C[bh,q,k] = mean_h cos(phq - phk)
//   = (cos_q @ cos_k^T + sin_q @ sin_k^T) / 64
// 16 GEMMs [2048,128]@[128,2048]^T in fp16 (validated rel_err ~5.6e-5).
// 1/64 folded into A scratch. Scratch row (K=128 fp16): cos[0:64] sin[64:128].
// R12 = R8 mainloop/epilogue (best, 74.0us) + multi-tile CTAs done RIGHT:
// 4 N-tiles per CTA, resident A, double-buffered B, 2 barriers/tile, direct
// .cs scatter epilogue overlapped with the next B load. Isolates the R5
// confound (multi-tile was only ever tested with the bad staged epilogue).
// ============================================================================

#define NBH 16
#define SEQ 2048
#define NH  64
#define KS  128          // scratch K width (cos 64 | sin 64)
#define BM  128
#define BN  128
#define TILES 4

// ---------------- scratch (device globals; no allocation APIs) --------------
__device__ __align__(16) __half gA[NBH * SEQ * KS];   // 8 MB (pre-scaled 1/64)
__device__ __align__(16) __half gB[NBH * SEQ * KS];   // 8 MB

__device__ __forceinline__ uint32_t smem_u32(const void* p) {
    uint32_t a;
    asm("{ .reg .u64 t; cvta.to.shared.u64 t, %1; cvt.u32.u64 %0, t; }"
        : "=r"(a) : "l"(p));
    return a;
}

#define CP_ASYNC_16(smem, gptr)                                                \
    asm volatile("cp.async.cg.shared.global [%0], [%1], 16;"                   \
                 :: "r"(smem), "l"(gptr))
#define CP_COMMIT()  asm volatile("cp.async.commit_group;" ::: "memory")
#define CP_WAIT(N)   asm volatile("cp.async.wait_group %0;" :: "n"(N) : "memory")

#define LDSM_X4(r0, r1, r2, r3, addr)                                          \
    asm volatile("ldmatrix.sync.aligned.m8n8.x4.shared.b16 {%0,%1,%2,%3}, [%4];" \
                 : "=r"(r0), "=r"(r1), "=r"(r2), "=r"(r3) : "r"(addr))

#define MMA_F16(c0, c1, c2, c3, a0, a1, a2, a3, b0, b1)                        \
    asm volatile("mma.sync.aligned.m16n8k16.row.col.f32.f16.f16.f32 "          \
                 "{%0,%1,%2,%3}, {%4,%5,%6,%7}, {%8,%9}, {%0,%1,%2,%3};"       \
                 : "+f"(c0), "+f"(c1), "+f"(c2), "+f"(c3)                      \
                 : "r"(a0), "r"(a1), "r"(a2), "r"(a3), "r"(b0), "r"(b1))

#define STG_CS_V2(gptr, x, y)                                                  \
    asm volatile("st.global.cs.v2.f32 [%0], {%1,%2};"                          \
                 :: "l"(gptr), "f"(x), "f"(y) : "memory")

// ============================================================================
// Kernel 1: __sincosf -> fp16 scratch (A pre-scaled 1/NH). 4 harmonics/thread.
// ============================================================================
__global__ void phase_prep_kernel(const float* __restrict__ q,
                                  const float* __restrict__ k)
{
    const int NT = NBH * SEQ * (NH / 4);    // 524288 threads per tensor
    int idx = blockIdx.x * blockDim.x + threadIdx.x;
    if (idx >= 2 * NT) return;
    bool isQ = idx < NT;
    int li  = isQ ? idx : idx - NT;
    int row = li >> 4;
    int h4  = (li & 15) << 2;

    const float4 v = *(const float4*)((isQ ? q : k) + (size_t)row * NH + h4);
    const float sc = isQ ? (1.0f / (float)NH) : 1.0f;

    float s0, c0, s1, c1, s2, c2, s3, c3;
    __sincosf(v.x, &s0, &c0);
    __sincosf(v.y, &s1, &c1);
    __sincosf(v.z, &s2, &c2);
    __sincosf(v.w, &s3, &c3);

    __half2 ca = __floats2half2_rn(c0 * sc, c1 * sc);
    __half2 cb = __floats2half2_rn(c2 * sc, c3 * sc);
    __half2 sa = __floats2half2_rn(s0 * sc, s1 * sc);
    __half2 sb = __floats2half2_rn(s2 * sc, s3 * sc);

    __half* dst = (isQ ? gA : gB) + (size_t)row * KS;
    uint2 uc, us;
    uc.x = *reinterpret_cast<uint32_t*>(&ca);
    uc.y = *reinterpret_cast<uint32_t*>(&cb);
    us.x = *reinterpret_cast<uint32_t*>(&sa);
    us.y = *reinterpret_cast<uint32_t*>(&sb);
    *(uint2*)(dst + h4)      = uc;
    *(uint2*)(dst + 64 + h4) = us;
}

// ============================================================================
// Kernel 2: fp16 mma.sync GEMM. grid (4,16,16)=1024 CTAs, 256 threads
// (2x4 warps of 64x32), 4 N-tiles per CTA.
// smem: A 32KB resident (256B rows) | B buf0 32KB | B buf1 32KB = 96KB.
// ============================================================================
#define A_BYTES 32768
#define B_BYTES 32768
#define SMEM_TOTAL (A_BYTES + 2 * B_BYTES)    // 98304

__global__ void __launch_bounds__(256, 2)
phase_gemm_kernel(float* __restrict__ out)
{
    extern __shared__ char smem[];
    const uint32_t sb = smem_u32(smem);
    const int tid  = threadIdx.x;
    const int wid  = tid >> 5;
    const int lane = tid & 31;
    const int wm   = wid >> 2;          // 0-1
    const int wn   = wid & 3;           // 0-3

    const int ntG = blockIdx.x;         // group of 4 N-tiles
    const int mt  = blockIdx.y;
    const int bh  = blockIdx.z;

    const __half* __restrict__ pA = gA + ((size_t)bh * SEQ + (size_t)mt * BM) * KS;
    const __half* __restrict__ pB0 =
        gB + ((size_t)bh * SEQ + (size_t)(ntG * TILES) * BN) * KS;

    // tile copy mapping: 2048 16B-chunks, idx = tid + t*256,
    // row = idx>>4, c = idx&15; sw = (c&8)|((c&7)^(row&7)); 256B rows.
    const int r0 = tid >> 4;             // +16 per t (t*16 % 8 == 0 -> sw invariant)
    const int c  = tid & 15;
    const uint32_t so0 = (uint32_t)(r0 * 256) +
                         ((uint32_t)((c & 8) | ((c & 7) ^ (r0 & 7))) << 4);
    const uint32_t go0 = (uint32_t)(r0 * KS + c * 8);   // elements

    // ---- prologue: A + B0 (group 0), B1 (group 1) ----
#pragma unroll
    for (int t = 0; t < 8; t++) {
        CP_ASYNC_16(sb + so0 + t * 4096,           pA  + go0 + t * 2048);
        CP_ASYNC_16(sb + A_BYTES + so0 + t * 4096, pB0 + go0 + t * 2048);
    }
    CP_COMMIT();
#pragma unroll
    for (int t = 0; t < 8; t++)
        CP_ASYNC_16(sb + A_BYTES + B_BYTES + so0 + t * 4096,
                    pB0 + (size_t)BN * KS + go0 + t * 2048);
    CP_COMMIT();

    // ldmatrix base rows
    const int rl = lane & 15;
    const int hc = lane >> 4;
    uint32_t aRow[4], bRow[2];
#pragma unroll
    for (int mf = 0; mf < 4; mf++) aRow[mf] = (uint32_t)(wm * 64 + mf * 16 + rl);
#pragma unroll
    for (int p = 0; p < 2; p++)   bRow[p]  = (uint32_t)(wn * 32 + p * 16 + rl);

    const int qg  = lane >> 2;
    const int cp2 = (lane & 3) * 2;
    float* const outMt = out + ((size_t)bh * SEQ + (size_t)mt * BM + wm * 64) * SEQ
                             + (size_t)(ntG * TILES) * BN + wn * 32;

#pragma unroll
    for (int i = 0; i < TILES; i++) {
        if (i < TILES - 1) { CP_WAIT(1); } else { CP_WAIT(0); }
        __syncthreads();

        float acc[4][4][4];
#pragma unroll
        for (int mf = 0; mf < 4; mf++)
#pragma unroll
            for (int nf = 0; nf < 4; nf++)
#pragma unroll
                for (int j = 0; j < 4; j++) acc[mf][nf][j] = 0.0f;

        const uint32_t bBase = sb + A_BYTES + (uint32_t)(i & 1) * B_BYTES;

        // ---- MMA: 8 k-slices of 16 (A resident at sb) ----
#pragma unroll
        for (int kk = 0; kk < 8; kk++) {
            const uint32_t ch = (uint32_t)(kk * 2 + hc);
            uint32_t a[4][4];
#pragma unroll
            for (int mf = 0; mf < 4; mf++) {
                uint32_t r = aRow[mf];
                uint32_t sw = (ch & 8) | ((ch & 7) ^ (r & 7));
                LDSM_X4(a[mf][0], a[mf][1], a[mf][2], a[mf][3],
                        sb + r * 256 + (sw << 4));
            }
            uint32_t b[4][2];
#pragma unroll
            for (int p = 0; p < 2; p++) {
                uint32_t r = bRow[p];
                uint32_t sw = (ch & 8) | ((ch & 7) ^ (r & 7));
                uint32_t x0, x1, x2, x3;
                LDSM_X4(x0, x1, x2, x3, bBase + r * 256 + (sw << 4));
                b[p * 2][0]     = x0; b[p * 2][1]     = x2;
                b[p * 2 + 1][0] = x1; b[p * 2 + 1][1] = x3;
            }
#pragma unroll
            for (int mf = 0; mf < 4; mf++)
#pragma unroll
                for (int nf = 0; nf < 4; nf++)
                    MMA_F16(acc[mf][nf][0], acc[mf][nf][1],
                            acc[mf][nf][2], acc[mf][nf][3],
                            a[mf][0], a[mf][1], a[mf][2], a[mf][3],
                            b[nf][0], b[nf][1]);
        }

        // ---- refill the just-read B buffer (needs all warps done) ----
        if (i < TILES - 2) {
            __syncthreads();
            const __half* pBn = pB0 + (size_t)(i + 2) * BN * KS;
            const uint32_t dst = sb + A_BYTES + (uint32_t)(i & 1) * B_BYTES;
#pragma unroll
            for (int t = 0; t < 8; t++)
                CP_ASYNC_16(dst + so0 + t * 4096, pBn + go0 + t * 2048);
            CP_COMMIT();
        }

        // ---- epilogue: direct .cs scatter (overlaps B(i+2) load) ----
        float* obase = outMt + (size_t)i * BN;
#pragma unroll
        for (int mf = 0; mf < 4; mf++) {
#pragma unroll
            for (int nf = 0; nf < 4; nf++) {
                float* p0 = obase + (size_t)(mf * 16 + qg) * SEQ + nf * 8 + cp2;
                STG_CS_V2(p0,           acc[mf][nf][0], acc[mf][nf][1]);
                STG_CS_V2(p0 + 8 * SEQ, acc[mf][nf][2], acc[mf][nf][3]);
            }
        }
    }
}

// ============================================================================
// launch
// ============================================================================
extern "C" void kernel_launch(void* const* d_in, const int* in_sizes, int n_in,
                              void* d_out, int out_size)
{
    const float* q = (const float*)d_in[0];
    const float* k = (const float*)d_in[1];
    float* out = (float*)d_out;

    cudaFuncSetAttribute(phase_gemm_kernel,
                         cudaFuncAttributeMaxDynamicSharedMemorySize, SMEM_TOTAL);

    const int NT = NBH * SEQ * (NH / 4);
    int threads = 256;
    int blocks = (2 * NT + threads - 1) / threads;
    phase_prep_kernel<<<blocks, threads>>>(q, k);

    dim3 grid(SEQ / BN / TILES, SEQ / BM, NBH);   // (4,16,16)
    phase_gemm_kernel<<<grid, 256, SMEM_TOTAL>>>(out);
}

// round 13
// speedup vs baseline: 1.2332x; 1.0593x over previous
#include <cuda_runtime.h>
#include <cuda_fp16.h>
#include <cstdint>

// ============================================================================
// PhaseCoherenceComputer: C[bh,q,k] = mean_h cos(phq - phk)
//   = (cos_q @ cos_k^T + sin_q @ sin_k^T) / 64
// 16 GEMMs [2048,128]@[128,2048]^T in fp16 (validated rel_err ~5.6e-5).
// 1/64 folded into A scratch. Scratch row (K=128 fp16): cos[0:64] sin[64:128].
// R13: small-CTA variant of R8. 128 threads (2x2 warps of 64x32), CTA tile
// 128x64, 48KB smem, 4 CTAs/SM (same 16 warps/SM as R8 but 4-warp barriers
// and 4 independent phase-interleaved CTAs per SM).
// ============================================================================

#define NBH 16
#define SEQ 2048
#define NH  64
#define KS  128          // scratch K width (cos 64 | sin 64)
#define BM  128
#define BN  64

// ---------------- scratch (device globals; no allocation APIs) --------------
__device__ __align__(16) __half gA[NBH * SEQ * KS];   // 8 MB (pre-scaled 1/64)
__device__ __align__(16) __half gB[NBH * SEQ * KS];   // 8 MB

__device__ __forceinline__ uint32_t smem_u32(const void* p) {
    uint32_t a;
    asm("{ .reg .u64 t; cvta.to.shared.u64 t, %1; cvt.u32.u64 %0, t; }"
        : "=r"(a) : "l"(p));
    return a;
}

#define CP_ASYNC_16(smem, gptr)                                                \
    asm volatile("cp.async.cg.shared.global [%0], [%1], 16;"                   \
                 :: "r"(smem), "l"(gptr))
#define CP_COMMIT()  asm volatile("cp.async.commit_group;" ::: "memory")
#define CP_WAIT(N)   asm volatile("cp.async.wait_group %0;" :: "n"(N) : "memory")

#define LDSM_X4(r0, r1, r2, r3, addr)                                          \
    asm volatile("ldmatrix.sync.aligned.m8n8.x4.shared.b16 {%0,%1,%2,%3}, [%4];" \
                 : "=r"(r0), "=r"(r1), "=r"(r2), "=r"(r3) : "r"(addr))

#define MMA_F16(c0, c1, c2, c3, a0, a1, a2, a3, b0, b1)                        \
    asm volatile("mma.sync.aligned.m16n8k16.row.col.f32.f16.f16.f32 "          \
                 "{%0,%1,%2,%3}, {%4,%5,%6,%7}, {%8,%9}, {%0,%1,%2,%3};"       \
                 : "+f"(c0), "+f"(c1), "+f"(c2), "+f"(c3)                      \
                 : "r"(a0), "r"(a1), "r"(a2), "r"(a3), "r"(b0), "r"(b1))

#define STG_CS_V2(gptr, x, y)                                                  \
    asm volatile("st.global.cs.v2.f32 [%0], {%1,%2};"                          \
                 :: "l"(gptr), "f"(x), "f"(y) : "memory")

// ============================================================================
// Kernel 1: __sincosf -> fp16 scratch (A pre-scaled 1/NH). 4 harmonics/thread.
// ============================================================================
__global__ void phase_prep_kernel(const float* __restrict__ q,
                                  const float* __restrict__ k)
{
    const int NT = NBH * SEQ * (NH / 4);    // 524288 threads per tensor
    int idx = blockIdx.x * blockDim.x + threadIdx.x;
    if (idx >= 2 * NT) return;
    bool isQ = idx < NT;
    int li  = isQ ? idx : idx - NT;
    int row = li >> 4;
    int h4  = (li & 15) << 2;

    const float4 v = *(const float4*)((isQ ? q : k) + (size_t)row * NH + h4);
    const float sc = isQ ? (1.0f / (float)NH) : 1.0f;

    float s0, c0, s1, c1, s2, c2, s3, c3;
    __sincosf(v.x, &s0, &c0);
    __sincosf(v.y, &s1, &c1);
    __sincosf(v.z, &s2, &c2);
    __sincosf(v.w, &s3, &c3);

    __half2 ca = __floats2half2_rn(c0 * sc, c1 * sc);
    __half2 cb = __floats2half2_rn(c2 * sc, c3 * sc);
    __half2 sa = __floats2half2_rn(s0 * sc, s1 * sc);
    __half2 sb = __floats2half2_rn(s2 * sc, s3 * sc);

    __half* dst = (isQ ? gA : gB) + (size_t)row * KS;
    uint2 uc, us;
    uc.x = *reinterpret_cast<uint32_t*>(&ca);
    uc.y = *reinterpret_cast<uint32_t*>(&cb);
    us.x = *reinterpret_cast<uint32_t*>(&sa);
    us.y = *reinterpret_cast<uint32_t*>(&sb);
    *(uint2*)(dst + h4)      = uc;
    *(uint2*)(dst + 64 + h4) = us;
}

// ============================================================================
// Kernel 2: fp16 mma.sync GEMM. CTA tile 128x64, 128 threads (2x2 warps of
// 64x32). grid = (32,16,16) = 8192 CTAs. smem: A 32KB + B 16KB (256B rows,
// XOR swizzle). All K loaded up-front, one wait+barrier, barrier-free
// mainloop, direct .cs scatter epilogue. 4 CTAs/SM.
// ============================================================================
#define A_BYTES (BM * 256)                    // 32768
#define B_BYTES (BN * 256)                    // 16384
#define SMEM_TOTAL (A_BYTES + B_BYTES)        // 49152

__global__ void __launch_bounds__(128, 4)
phase_gemm_kernel(float* __restrict__ out)
{
    extern __shared__ char smem[];
    const uint32_t sb = smem_u32(smem);
    const int tid  = threadIdx.x;
    const int wid  = tid >> 5;
    const int lane = tid & 31;
    const int wm   = wid >> 1;          // 0-1
    const int wn   = wid & 1;           // 0-1

    const int nt = blockIdx.x;          // 64-wide N tile
    const int mt = blockIdx.y;
    const int bh = blockIdx.z;

    const __half* __restrict__ pA = gA + ((size_t)bh * SEQ + (size_t)mt * BM) * KS;
    const __half* __restrict__ pB = gB + ((size_t)bh * SEQ + (size_t)nt * BN) * KS;

    // tile copy: rows of 256B = 16 chunks; idx = tid + t*128 -> row = idx>>4
    // (advances 8/t, multiple of 8 -> swizzle invariant), chunk c = tid&15.
    const int r0 = tid >> 4;             // 0-7
    const int c  = tid & 15;
    const uint32_t so0 = (uint32_t)(r0 * 256) +
                         ((uint32_t)((c & 8) | ((c & 7) ^ (r0 & 7))) << 4);
    const uint32_t go0 = (uint32_t)(r0 * KS + c * 8);   // elements

    // ---- load A (16 iters) + B (8 iters), single commit ----
#pragma unroll
    for (int t = 0; t < 16; t++)
        CP_ASYNC_16(sb + so0 + t * 2048, pA + go0 + t * 1024);
#pragma unroll
    for (int t = 0; t < 8; t++)
        CP_ASYNC_16(sb + A_BYTES + so0 + t * 2048, pB + go0 + t * 1024);
    CP_COMMIT();

    // ldmatrix base rows
    const int rl = lane & 15;
    const int hc = lane >> 4;
    uint32_t aRow[4], bRow[2];
#pragma unroll
    for (int mf = 0; mf < 4; mf++) aRow[mf] = (uint32_t)(wm * 64 + mf * 16 + rl);
#pragma unroll
    for (int p = 0; p < 2; p++)   bRow[p]  = (uint32_t)(wn * 32 + p * 16 + rl);

    float acc[4][4][4];
#pragma unroll
    for (int mf = 0; mf < 4; mf++)
#pragma unroll
        for (int nf = 0; nf < 4; nf++)
#pragma unroll
            for (int j = 0; j < 4; j++) acc[mf][nf][j] = 0.0f;

    // ---- single wait + 4-warp barrier, then barrier-free mainloop ----
    CP_WAIT(0);
    __syncthreads();

#pragma unroll
    for (int kk = 0; kk < 8; kk++) {
        const uint32_t ch = (uint32_t)(kk * 2 + hc);   // 0-15
        uint32_t a[4][4];
#pragma unroll
        for (int mf = 0; mf < 4; mf++) {
            uint32_t r = aRow[mf];
            uint32_t sw = (ch & 8) | ((ch & 7) ^ (r & 7));
            LDSM_X4(a[mf][0], a[mf][1], a[mf][2], a[mf][3],
                    sb + r * 256 + (sw << 4));
        }
        uint32_t b[4][2];
#pragma unroll
        for (int p = 0; p < 2; p++) {
            uint32_t r = bRow[p];
            uint32_t sw = (ch & 8) | ((ch & 7) ^ (r & 7));
            uint32_t x0, x1, x2, x3;
            LDSM_X4(x0, x1, x2, x3, sb + A_BYTES + r * 256 + (sw << 4));
            b[p * 2][0]     = x0; b[p * 2][1]     = x2;
            b[p * 2 + 1][0] = x1; b[p * 2 + 1][1] = x3;
        }
#pragma unroll
        for (int mf = 0; mf < 4; mf++)
#pragma unroll
            for (int nf = 0; nf < 4; nf++)
                MMA_F16(acc[mf][nf][0], acc[mf][nf][1],
                        acc[mf][nf][2], acc[mf][nf][3],
                        a[mf][0], a[mf][1], a[mf][2], a[mf][3],
                        b[nf][0], b[nf][1]);
    }

    // ---- epilogue: direct .cs scatter (scale pre-folded into A) ----
    const int qg  = lane >> 2;
    const int cp2 = (lane & 3) * 2;
    float* obase = out + ((size_t)bh * SEQ + (size_t)mt * BM + wm * 64) * SEQ
                       + (size_t)nt * BN + wn * 32;
#pragma unroll
    for (int mf = 0; mf < 4; mf++) {
#pragma unroll
        for (int nf = 0; nf < 4; nf++) {
            float* p0 = obase + (size_t)(mf * 16 + qg) * SEQ + nf * 8 + cp2;
            STG_CS_V2(p0,           acc[mf][nf][0], acc[mf][nf][1]);
            STG_CS_V2(p0 + 8 * SEQ, acc[mf][nf][2], acc[mf][nf][3]);
        }
    }
}

// ============================================================================
// launch
// ============================================================================
extern "C" void kernel_launch(void* const* d_in, const int* in_sizes, int n_in,
                              void* d_out, int out_size)
{
    const float* q = (const float*)d_in[0];
    const float* k = (const float*)d_in[1];
    float* out = (float*)d_out;

    cudaFuncSetAttribute(phase_gemm_kernel,
                         cudaFuncAttributeMaxDynamicSharedMemorySize, SMEM_TOTAL);

    const int NT = NBH * SEQ * (NH / 4);
    int threads = 256;
    int blocks = (2 * NT + threads - 1) / threads;
    phase_prep_kernel<<<blocks, threads>>>(q, k);

    dim3 grid(SEQ / BN, SEQ / BM, NBH);   // (32,16,16)
    phase_gemm_kernel<<<grid, 128, SMEM_TOTAL>>>(out);
}